// round 12
// baseline (speedup 1.0000x reference)
#include <cuda_runtime.h>
#include <cuda_fp16.h>
#include <cuda_bf16.h>
#include <cstdint>
#include <cstddef>

#define NN 100000
#define EE 1600000
#define DD 64
#define KPROP 10
#define SC 1024          // elements per scan block

// ---------------- scratch (static device globals; no runtime allocation) ----
__device__ float  g_deg[NN];
__device__ float  g_dinv[NN];
__device__ float  g_selfw[NN];
__device__ int    g_cnt[NN];
__device__ int    g_rowptr[NN + 1];
__device__ int    g_bsum[128];
__device__ int    g_boff[128];
__device__ int    g_cols[EE];
__device__ float  g_wn[EE];
__device__ __align__(16) __half g_x16[NN * DD];   // fp16 copy of x
__device__ __align__(16) __half g_h16A[NN * DD];  // ping
__device__ __align__(16) __half g_h16B[NN * DD];  // pong
__device__ __align__(16) float  g_acc[NN * DD];   // fp32 acc of sum_l A^l x
__device__ __align__(16) __half g_y16[NN * DD];   // fp16(0.1x + 0.09acc)
__device__ __align__(16) __half g_z16[NN * 256];  // fp16 hidden layer
__device__ __align__(16) __half g_w0t[256 * 64];  // W0^T fp16 [N][K]
__device__ __align__(16) __half g_w1t[64 * 256];  // W1^T fp16 [N][K]

// ---------------- fused: deg=1, cnt=0, x->fp16 -------------------------------
__global__ void init_cvt_kernel(const float* __restrict__ x, int n, int n2) {
    int i = blockIdx.x * blockDim.x + threadIdx.x;
    if (i < n) { g_deg[i] = 1.0f; g_cnt[i] = 0; }
    if (i < n2) {
        float2 f = ((const float2*)x)[i];
        ((__half2*)g_x16)[i] = __floats2half2_rn(f.x, f.y);
    }
}

// ---------------- degree + row histogram ------------------------------------
__global__ void hist_kernel(const int* __restrict__ row,
                            const float* __restrict__ w, int e) {
    int i = blockIdx.x * blockDim.x + threadIdx.x;
    if (i < e) {
        int r = row[i];
        atomicAdd(&g_deg[r], w[i]);
        atomicAdd(&g_cnt[r], 1);
    }
}

// ---------------- dinv + self-loop weight -----------------------------------
__global__ void dinv_kernel(int n) {
    int i = blockIdx.x * blockDim.x + threadIdx.x;
    if (i < n) {
        float di = rsqrtf(fmaxf(g_deg[i], 1e-12f));
        g_dinv[i] = di;
        g_selfw[i] = di * di;
    }
}

// ---------------- W0 [64,256] -> w0t fp16 [256,64]; W1 [256,64] -> w1t ------
__global__ void wconv_kernel(const float* __restrict__ W0,
                             const float* __restrict__ W1) {
    int i = blockIdx.x * blockDim.x + threadIdx.x;
    if (i < 64 * 256) {
        int k = i >> 8, nn = i & 255;          // i = k*256 + n
        g_w0t[nn * 64 + k] = __float2half(W0[i]);
    }
    if (i < 256 * 64) {
        int k = i >> 6, nn = i & 63;           // i = k*64 + n
        g_w1t[nn * 256 + k] = __float2half(W1[i]);
    }
}

// ---------------- parallel scan: A (block sums) -----------------------------
__global__ void scanA_kernel(int n) {
    int b = blockIdx.x;
    int t = threadIdx.x;
    int base = b * SC + t * 4;
    int s = 0;
#pragma unroll
    for (int k = 0; k < 4; ++k) {
        int i = base + k;
        if (i < n) s += g_cnt[i];
    }
#pragma unroll
    for (int off = 16; off; off >>= 1)
        s += __shfl_down_sync(0xffffffffu, s, off);
    __shared__ int ws[8];
    if ((t & 31) == 0) ws[t >> 5] = s;
    __syncthreads();
    if (t < 8) {
        int v = ws[t];
#pragma unroll
        for (int off = 4; off; off >>= 1)
            v += __shfl_down_sync(0xffu, v, off);
        if (t == 0) g_bsum[b] = v;
    }
}

// ---------------- parallel scan: B (scan 98 block sums, one block) ----------
__global__ void scanB_kernel(int nb, int n) {
    __shared__ int sm[128];
    int t = threadIdx.x;
    int v = (t < nb) ? g_bsum[t] : 0;
    sm[t] = v;
    __syncthreads();
    for (int off = 1; off < 128; off <<= 1) {
        int u = (t >= off) ? sm[t - off] : 0;
        __syncthreads();
        sm[t] += u;
        __syncthreads();
    }
    if (t < nb) g_boff[t] = sm[t] - v;      // exclusive offset
    if (t == nb - 1) g_rowptr[n] = sm[t];   // total edge count
}

// ---------------- parallel scan: C (local scan + offset, reset cnt) ---------
__global__ void scanC_kernel(int n) {
    int b = blockIdx.x;
    int t = threadIdx.x;
    int lane = t & 31, wid = t >> 5;
    int base = b * SC + t * 4;

    int vals[4];
    int s = 0;
#pragma unroll
    for (int k = 0; k < 4; ++k) {
        int i = base + k;
        vals[k] = (i < n) ? g_cnt[i] : 0;
        s += vals[k];
    }
    int ss = s;
#pragma unroll
    for (int off = 1; off < 32; off <<= 1) {
        int u = __shfl_up_sync(0xffffffffu, ss, off);
        if (lane >= off) ss += u;
    }
    __shared__ int wtot[8];
    if (lane == 31) wtot[wid] = ss;
    __syncthreads();
    if (t == 0) {
        int run = 0;
#pragma unroll
        for (int wq = 0; wq < 8; ++wq) { int tmp = wtot[wq]; wtot[wq] = run; run += tmp; }
    }
    __syncthreads();
    int ex = ss - s + wtot[wid] + g_boff[b];
#pragma unroll
    for (int k = 0; k < 4; ++k) {
        int i = base + k;
        if (i < n) {
            g_rowptr[i] = ex;
            ex += vals[k];
            g_cnt[i] = 0;   // reset: reused as scatter cursors
        }
    }
}

// ---------------- scatter edges into CSR with normalized weights ------------
__global__ void scatter_kernel(const int* __restrict__ row,
                               const int* __restrict__ col,
                               const float* __restrict__ w, int e) {
    int i = blockIdx.x * blockDim.x + threadIdx.x;
    if (i < e) {
        int r = row[i];
        int c = col[i];
        int pos = g_rowptr[r] + atomicAdd(&g_cnt[r], 1);
        g_cols[pos] = c;
        g_wn[pos] = g_dinv[r] * w[i] * g_dinv[c];
    }
}

// ---------------- SpMM step: warp per row, 8 lanes/edge, 4 edges/pass -------
// Own-row / acc-row / x-row loads PREFETCHED before the edge loop so their
// L2 latency overlaps the gathers (they were serial epilogue round-trips).
// Last iteration fuses the alpha-mix: writes y16 = fp16(0.1 x + 0.09 acc),
// skips hout/acc stores (ymix kernel eliminated).
__global__ void spmm_kernel(const float* __restrict__ x, int iter, int n) {
    int gw = (blockIdx.x * blockDim.x + threadIdx.x) >> 5;
    if (gw >= n) return;
    int lane = threadIdx.x & 31;
    int g   = lane >> 3;   // edge group 0..3
    int sub = lane & 7;    // 16B chunk within 128B row

    const uint4* __restrict__ hin4 =
        (iter == 0) ? (const uint4*)g_x16
                    : ((iter & 1) ? (const uint4*)g_h16A
                                  : (const uint4*)g_h16B);
    uint4* __restrict__ hout4 =
        (iter & 1) ? (uint4*)g_h16B : (uint4*)g_h16A;

    bool last = (iter == KPROP - 1);
    float4* accp = (float4*)g_acc;
    size_t ai = (size_t)gw * 16 + sub * 2;

    // ---- prefetch independent row data (lanes 0-7 only need it) ----
    uint4 own = make_uint4(0, 0, 0, 0);
    float4 t0 = make_float4(0.f, 0.f, 0.f, 0.f);
    float4 t1 = make_float4(0.f, 0.f, 0.f, 0.f);
    float4 xf0 = make_float4(0.f, 0.f, 0.f, 0.f);
    float4 xf1 = make_float4(0.f, 0.f, 0.f, 0.f);
    if (lane < 8) {
        own = hin4[(size_t)gw * 8 + sub];
        if (iter > 0) { t0 = accp[ai]; t1 = accp[ai + 1]; }
        if (last) {
            xf0 = ((const float4*)x)[ai];
            xf1 = ((const float4*)x)[ai + 1];
        }
    }

    float acc[8];
#pragma unroll
    for (int k = 0; k < 8; ++k) acc[k] = 0.0f;

    int s = g_rowptr[gw];
    int e = g_rowptr[gw + 1];
    int d = e - s;
    int full = d >> 2;
    int epb = s + g;

#pragma unroll 4
    for (int j = 0; j < full; ++j) {
        int ep = epb + j * 4;
        int   cc = __ldg(&g_cols[ep]);
        float ww = __ldg(&g_wn[ep]);
        uint4 v = hin4[(size_t)cc * 8 + sub];
        const __half2* hp = (const __half2*)&v;
#pragma unroll
        for (int q = 0; q < 4; ++q) {
            float2 f = __half22float2(hp[q]);
            acc[2 * q]     = fmaf(ww, f.x, acc[2 * q]);
            acc[2 * q + 1] = fmaf(ww, f.y, acc[2 * q + 1]);
        }
    }
    int r = d & 3;
    if (r) {
        int ep = epb + full * 4;
        int cc = 0;
        float ww = 0.0f;
        if (g < r) { cc = g_cols[ep]; ww = g_wn[ep]; }
        uint4 v = hin4[(size_t)cc * 8 + sub];
        const __half2* hp = (const __half2*)&v;
#pragma unroll
        for (int q = 0; q < 4; ++q) {
            float2 f = __half22float2(hp[q]);
            acc[2 * q]     = fmaf(ww, f.x, acc[2 * q]);
            acc[2 * q + 1] = fmaf(ww, f.y, acc[2 * q + 1]);
        }
    }

    // reduce the 4 edge groups (lanes differ in bits 3,4)
#pragma unroll
    for (int off = 8; off <= 16; off <<= 1)
#pragma unroll
        for (int k = 0; k < 8; ++k)
            acc[k] += __shfl_xor_sync(0xffffffffu, acc[k], off);

    if (lane < 8) {
        // self-loop contribution from prefetched own row
        float sw = g_selfw[gw];
        const __half2* op = (const __half2*)&own;
#pragma unroll
        for (int q = 0; q < 4; ++q) {
            float2 f = __half22float2(op[q]);
            acc[2 * q]     = fmaf(sw, f.x, acc[2 * q]);
            acc[2 * q + 1] = fmaf(sw, f.y, acc[2 * q + 1]);
        }
        // running fp32 accumulator (prefetched)
        if (iter > 0) {
            acc[0] += t0.x; acc[1] += t0.y; acc[2] += t0.z; acc[3] += t0.w;
            acc[4] += t1.x; acc[5] += t1.y; acc[6] += t1.z; acc[7] += t1.w;
        }
        // NOTE: acc[] now holds the NEW running sum; h_new for next iter is
        // acc_new - acc_old... no: h_new is this iter's propagation only.
        // Keep them separate: recompute h_new = acc - t (only when storing).
        if (!last) {
            uint4 outv;
            __half2* ov = (__half2*)&outv;
            float h0 = acc[0] - t0.x, h1 = acc[1] - t0.y;
            float h2 = acc[2] - t0.z, h3 = acc[3] - t0.w;
            float h4 = acc[4] - t1.x, h5 = acc[5] - t1.y;
            float h6 = acc[6] - t1.z, h7 = acc[7] - t1.w;
            ov[0] = __floats2half2_rn(h0, h1);
            ov[1] = __floats2half2_rn(h2, h3);
            ov[2] = __floats2half2_rn(h4, h5);
            ov[3] = __floats2half2_rn(h6, h7);
            hout4[(size_t)gw * 8 + sub] = outv;
            accp[ai]     = make_float4(acc[0], acc[1], acc[2], acc[3]);
            accp[ai + 1] = make_float4(acc[4], acc[5], acc[6], acc[7]);
        } else {
            // fused alpha-mix: y = 0.1*x + (0.9/K)*acc_final
            const float A = 0.1f, B = 0.09f;
            uint4 yv;
            __half2* yp = (__half2*)&yv;
            yp[0] = __floats2half2_rn(A * xf0.x + B * acc[0],
                                      A * xf0.y + B * acc[1]);
            yp[1] = __floats2half2_rn(A * xf0.z + B * acc[2],
                                      A * xf0.w + B * acc[3]);
            yp[2] = __floats2half2_rn(A * xf1.x + B * acc[4],
                                      A * xf1.y + B * acc[5]);
            yp[3] = __floats2half2_rn(A * xf1.z + B * acc[6],
                                      A * xf1.w + B * acc[7]);
            ((uint4*)g_y16)[(size_t)gw * 8 + sub] = yv;
        }
    }
}

// ---------------- mma.m16n8k16 wrapper ---------------------------------------
__device__ __forceinline__ void mma16816(float* c, uint32_t a0, uint32_t a1,
                                         uint32_t a2, uint32_t a3,
                                         uint32_t b0, uint32_t b1) {
    asm volatile(
        "mma.sync.aligned.m16n8k16.row.col.f32.f16.f16.f32 "
        "{%0,%1,%2,%3}, {%4,%5,%6,%7}, {%8,%9}, {%0,%1,%2,%3};"
        : "+f"(c[0]), "+f"(c[1]), "+f"(c[2]), "+f"(c[3])
        : "r"(a0), "r"(a1), "r"(a2), "r"(a3), "r"(b0), "r"(b1));
}

// ---------------- GEMM1 (tensor core): z16 = relu(y16 @ W0 + b0) ------------
__global__ void gemm1_mma(const float* __restrict__ b0v, int M) {
    int tid = threadIdx.x;
    int wid = tid >> 5, lane = tid & 31;
    int gid = lane >> 2, tig = lane & 3;
    int m0 = blockIdx.x * 128 + wid * 16;
    int n0 = blockIdx.y * 32;

    float c[4][4];
#pragma unroll
    for (int i = 0; i < 4; ++i)
#pragma unroll
        for (int j = 0; j < 4; ++j) c[i][j] = 0.0f;

    int rA0 = min(m0 + gid, M - 1);
    int rA1 = min(m0 + gid + 8, M - 1);
    const __half* Y = g_y16;
    const __half* W = g_w0t;

#pragma unroll
    for (int ks = 0; ks < 4; ++ks) {
        int kb = ks * 16 + tig * 2;
        uint32_t a0 = *(const uint32_t*)&Y[rA0 * 64 + kb];
        uint32_t a1 = *(const uint32_t*)&Y[rA1 * 64 + kb];
        uint32_t a2 = *(const uint32_t*)&Y[rA0 * 64 + kb + 8];
        uint32_t a3 = *(const uint32_t*)&Y[rA1 * 64 + kb + 8];
#pragma unroll
        for (int nf = 0; nf < 4; ++nf) {
            int nn = n0 + nf * 8 + gid;
            uint32_t b0 = *(const uint32_t*)&W[nn * 64 + kb];
            uint32_t b1 = *(const uint32_t*)&W[nn * 64 + kb + 8];
            mma16816(c[nf], a0, a1, a2, a3, b0, b1);
        }
    }

    int r0 = m0 + gid;
    int r1 = r0 + 8;
#pragma unroll
    for (int nf = 0; nf < 4; ++nf) {
        int cn = n0 + nf * 8 + tig * 2;
        float2 bias = *(const float2*)&b0v[cn];
        if (r0 < M) {
            __half2 h = __floats2half2_rn(fmaxf(c[nf][0] + bias.x, 0.0f),
                                          fmaxf(c[nf][1] + bias.y, 0.0f));
            *(__half2*)&g_z16[(size_t)r0 * 256 + cn] = h;
        }
        if (r1 < M) {
            __half2 h = __floats2half2_rn(fmaxf(c[nf][2] + bias.x, 0.0f),
                                          fmaxf(c[nf][3] + bias.y, 0.0f));
            *(__half2*)&g_z16[(size_t)r1 * 256 + cn] = h;
        }
    }
}

// ---------------- GEMM2 (tensor core): out = z16 @ W1 + b1 ------------------
__global__ void gemm2_mma(const float* __restrict__ b1v,
                          float* __restrict__ out, int M) {
    int tid = threadIdx.x;
    int wid = tid >> 5, lane = tid & 31;
    int gid = lane >> 2, tig = lane & 3;
    int m0 = blockIdx.x * 128 + wid * 16;
    int n0 = blockIdx.y * 32;

    float c[4][4];
#pragma unroll
    for (int i = 0; i < 4; ++i)
#pragma unroll
        for (int j = 0; j < 4; ++j) c[i][j] = 0.0f;

    int rA0 = min(m0 + gid, M - 1);
    int rA1 = min(m0 + gid + 8, M - 1);
    const __half* Z = g_z16;
    const __half* W = g_w1t;

#pragma unroll
    for (int ks = 0; ks < 16; ++ks) {
        int kb = ks * 16 + tig * 2;
        uint32_t a0 = *(const uint32_t*)&Z[(size_t)rA0 * 256 + kb];
        uint32_t a1 = *(const uint32_t*)&Z[(size_t)rA1 * 256 + kb];
        uint32_t a2 = *(const uint32_t*)&Z[(size_t)rA0 * 256 + kb + 8];
        uint32_t a3 = *(const uint32_t*)&Z[(size_t)rA1 * 256 + kb + 8];
#pragma unroll
        for (int nf = 0; nf < 4; ++nf) {
            int nn = n0 + nf * 8 + gid;
            uint32_t b0 = *(const uint32_t*)&W[nn * 256 + kb];
            uint32_t b1 = *(const uint32_t*)&W[nn * 256 + kb + 8];
            mma16816(c[nf], a0, a1, a2, a3, b0, b1);
        }
    }

    int r0 = m0 + gid;
    int r1 = r0 + 8;
#pragma unroll
    for (int nf = 0; nf < 4; ++nf) {
        int cn = n0 + nf * 8 + tig * 2;
        float2 bias = *(const float2*)&b1v[cn];
        if (r0 < M) {
            float2 o = make_float2(c[nf][0] + bias.x, c[nf][1] + bias.y);
            *(float2*)&out[(size_t)r0 * 64 + cn] = o;
        }
        if (r1 < M) {
            float2 o = make_float2(c[nf][2] + bias.x, c[nf][3] + bias.y);
            *(float2*)&out[(size_t)r1 * 64 + cn] = o;
        }
    }
}

// ---------------- launcher ---------------------------------------------------
extern "C" void kernel_launch(void* const* d_in, const int* in_sizes, int n_in,
                              void* d_out, int out_size) {
    const float* x  = (const float*)d_in[0];
    const int*   ei = (const int*)d_in[1];
    const float* ew = (const float*)d_in[2];
    const float* W0 = (const float*)d_in[3];
    const float* b0 = (const float*)d_in[4];
    const float* W1 = (const float*)d_in[5];
    const float* b1 = (const float*)d_in[6];
    float* out = (float*)d_out;

    int n = in_sizes[0] / DD;
    int e = in_sizes[2];
    const int* row = ei;
    const int* col = ei + e;

    int n2 = n * DD / 2;
    int nb = (n + SC - 1) / SC;   // scan blocks (98 for n=100000)

    init_cvt_kernel<<<(n2 + 255) / 256, 256>>>(x, n, n2);
    hist_kernel<<<(e + 255) / 256, 256>>>(row, ew, e);
    dinv_kernel<<<(n + 255) / 256, 256>>>(n);
    wconv_kernel<<<64, 256>>>(W0, W1);
    scanA_kernel<<<nb, 256>>>(n);
    scanB_kernel<<<1, 128>>>(nb, n);
    scanC_kernel<<<nb, 256>>>(n);
    scatter_kernel<<<(e + 255) / 256, 256>>>(row, col, ew, e);

    int spmm_grid = (n + 7) / 8;   // 8 warps (rows) per 256-thread block
    for (int it = 0; it < KPROP; ++it)
        spmm_kernel<<<spmm_grid, 256>>>(x, it, n);

    int mblocks = (n + 127) / 128;
    gemm1_mma<<<dim3(mblocks, 8), 256>>>(b0, n);
    gemm2_mma<<<dim3(mblocks, 2), 256>>>(b1, out, n);
}

// round 15
// speedup vs baseline: 1.6631x; 1.6631x over previous
#include <cuda_runtime.h>
#include <cuda_fp16.h>
#include <cuda_bf16.h>
#include <cstdint>
#include <cstddef>

#define NN 100000
#define EE 1600000
#define DD 64
#define KPROP 10
#define SC 1024          // elements per scan block

// ---------------- scratch (static device globals; no runtime allocation) ----
__device__ float  g_deg[NN];
__device__ float  g_dinv[NN];
__device__ float  g_selfw[NN];
__device__ int    g_cnt[NN];
__device__ int    g_rowptr[NN + 1];
__device__ int    g_bsum[128];
__device__ int    g_boff[128];
__device__ int    g_cols[EE];
__device__ float  g_wn[EE];
__device__ __align__(16) __half g_x16[NN * DD];   // fp16 copy of x
__device__ __align__(16) __half g_h16A[NN * DD];  // ping
__device__ __align__(16) __half g_h16B[NN * DD];  // pong
__device__ __align__(16) float  g_acc[NN * DD];   // fp32 acc of sum_l A^l x
__device__ __align__(16) __half g_y16[NN * DD];   // fp16(0.1x + 0.09acc)
__device__ __align__(16) __half g_z16[NN * 256];  // fp16 hidden layer
__device__ __align__(16) __half g_w0t[256 * 64];  // W0^T fp16 [N][K]
__device__ __align__(16) __half g_w1t[64 * 256];  // W1^T fp16 [N][K]

// ---------------- fused: deg=1, cnt=0, x->fp16 -------------------------------
__global__ void init_cvt_kernel(const float* __restrict__ x, int n, int n2) {
    int i = blockIdx.x * blockDim.x + threadIdx.x;
    if (i < n) { g_deg[i] = 1.0f; g_cnt[i] = 0; }
    if (i < n2) {
        float2 f = ((const float2*)x)[i];
        ((__half2*)g_x16)[i] = __floats2half2_rn(f.x, f.y);
    }
}

// ---------------- degree + row histogram ------------------------------------
__global__ void hist_kernel(const int* __restrict__ row,
                            const float* __restrict__ w, int e) {
    int i = blockIdx.x * blockDim.x + threadIdx.x;
    if (i < e) {
        int r = row[i];
        atomicAdd(&g_deg[r], w[i]);
        atomicAdd(&g_cnt[r], 1);
    }
}

// ---------------- dinv + self-loop weight -----------------------------------
__global__ void dinv_kernel(int n) {
    int i = blockIdx.x * blockDim.x + threadIdx.x;
    if (i < n) {
        float di = rsqrtf(fmaxf(g_deg[i], 1e-12f));
        g_dinv[i] = di;
        g_selfw[i] = di * di;
    }
}

// ---------------- W0 [64,256] -> w0t fp16 [256,64]; W1 [256,64] -> w1t ------
__global__ void wconv_kernel(const float* __restrict__ W0,
                             const float* __restrict__ W1) {
    int i = blockIdx.x * blockDim.x + threadIdx.x;
    if (i < 64 * 256) {
        int k = i >> 8, nn = i & 255;          // i = k*256 + n
        g_w0t[nn * 64 + k] = __float2half(W0[i]);
    }
    if (i < 256 * 64) {
        int k = i >> 6, nn = i & 63;           // i = k*64 + n
        g_w1t[nn * 256 + k] = __float2half(W1[i]);
    }
}

// ---------------- parallel scan: A (block sums) -----------------------------
__global__ void scanA_kernel(int n) {
    int b = blockIdx.x;
    int t = threadIdx.x;
    int base = b * SC + t * 4;
    int s = 0;
#pragma unroll
    for (int k = 0; k < 4; ++k) {
        int i = base + k;
        if (i < n) s += g_cnt[i];
    }
#pragma unroll
    for (int off = 16; off; off >>= 1)
        s += __shfl_down_sync(0xffffffffu, s, off);
    __shared__ int ws[8];
    if ((t & 31) == 0) ws[t >> 5] = s;
    __syncthreads();
    if (t < 8) {
        int v = ws[t];
#pragma unroll
        for (int off = 4; off; off >>= 1)
            v += __shfl_down_sync(0xffu, v, off);
        if (t == 0) g_bsum[b] = v;
    }
}

// ---------------- parallel scan: B (scan 98 block sums, one block) ----------
__global__ void scanB_kernel(int nb, int n) {
    __shared__ int sm[128];
    int t = threadIdx.x;
    int v = (t < nb) ? g_bsum[t] : 0;
    sm[t] = v;
    __syncthreads();
    for (int off = 1; off < 128; off <<= 1) {
        int u = (t >= off) ? sm[t - off] : 0;
        __syncthreads();
        sm[t] += u;
        __syncthreads();
    }
    if (t < nb) g_boff[t] = sm[t] - v;      // exclusive offset
    if (t == nb - 1) g_rowptr[n] = sm[t];   // total edge count
}

// ---------------- parallel scan: C (local scan + offset, reset cnt) ---------
__global__ void scanC_kernel(int n) {
    int b = blockIdx.x;
    int t = threadIdx.x;
    int lane = t & 31, wid = t >> 5;
    int base = b * SC + t * 4;

    int vals[4];
    int s = 0;
#pragma unroll
    for (int k = 0; k < 4; ++k) {
        int i = base + k;
        vals[k] = (i < n) ? g_cnt[i] : 0;
        s += vals[k];
    }
    int ss = s;
#pragma unroll
    for (int off = 1; off < 32; off <<= 1) {
        int u = __shfl_up_sync(0xffffffffu, ss, off);
        if (lane >= off) ss += u;
    }
    __shared__ int wtot[8];
    if (lane == 31) wtot[wid] = ss;
    __syncthreads();
    if (t == 0) {
        int run = 0;
#pragma unroll
        for (int wq = 0; wq < 8; ++wq) { int tmp = wtot[wq]; wtot[wq] = run; run += tmp; }
    }
    __syncthreads();
    int ex = ss - s + wtot[wid] + g_boff[b];
#pragma unroll
    for (int k = 0; k < 4; ++k) {
        int i = base + k;
        if (i < n) {
            g_rowptr[i] = ex;
            ex += vals[k];
            g_cnt[i] = 0;   // reset: reused as scatter cursors
        }
    }
}

// ---------------- scatter edges into CSR with normalized weights ------------
__global__ void scatter_kernel(const int* __restrict__ row,
                               const int* __restrict__ col,
                               const float* __restrict__ w, int e) {
    int i = blockIdx.x * blockDim.x + threadIdx.x;
    if (i < e) {
        int r = row[i];
        int c = col[i];
        int pos = g_rowptr[r] + atomicAdd(&g_cnt[r], 1);
        g_cols[pos] = c;
        g_wn[pos] = g_dinv[r] * w[i] * g_dinv[c];
    }
}

// ---------------- SpMM step: warp per row, 8 lanes/edge, 4 edges/pass -------
// (R11 version, known-good; R12 prefetch variant regressed and was reverted)
__global__ void spmm_kernel(int iter, int n) {
    int gw = (blockIdx.x * blockDim.x + threadIdx.x) >> 5;
    if (gw >= n) return;
    int lane = threadIdx.x & 31;
    int g   = lane >> 3;   // edge group 0..3
    int sub = lane & 7;    // 16B chunk within 128B row

    const uint4* __restrict__ hin4 =
        (iter == 0) ? (const uint4*)g_x16
                    : ((iter & 1) ? (const uint4*)g_h16A
                                  : (const uint4*)g_h16B);
    uint4* __restrict__ hout4 =
        (iter & 1) ? (uint4*)g_h16B : (uint4*)g_h16A;

    float acc[8];
#pragma unroll
    for (int k = 0; k < 8; ++k) acc[k] = 0.0f;

    int s = g_rowptr[gw];
    int e = g_rowptr[gw + 1];
    int d = e - s;
    int full = d >> 2;
    int epb = s + g;

#pragma unroll 4
    for (int j = 0; j < full; ++j) {
        int ep = epb + j * 4;
        int   cc = __ldg(&g_cols[ep]);
        float ww = __ldg(&g_wn[ep]);
        uint4 v = hin4[(size_t)cc * 8 + sub];
        const __half2* hp = (const __half2*)&v;
#pragma unroll
        for (int q = 0; q < 4; ++q) {
            float2 f = __half22float2(hp[q]);
            acc[2 * q]     = fmaf(ww, f.x, acc[2 * q]);
            acc[2 * q + 1] = fmaf(ww, f.y, acc[2 * q + 1]);
        }
    }
    int r = d & 3;
    if (r) {
        int ep = epb + full * 4;
        int cc = 0;
        float ww = 0.0f;
        if (g < r) { cc = g_cols[ep]; ww = g_wn[ep]; }
        uint4 v = hin4[(size_t)cc * 8 + sub];
        const __half2* hp = (const __half2*)&v;
#pragma unroll
        for (int q = 0; q < 4; ++q) {
            float2 f = __half22float2(hp[q]);
            acc[2 * q]     = fmaf(ww, f.x, acc[2 * q]);
            acc[2 * q + 1] = fmaf(ww, f.y, acc[2 * q + 1]);
        }
    }

#pragma unroll
    for (int off = 8; off <= 16; off <<= 1)
#pragma unroll
        for (int k = 0; k < 8; ++k)
            acc[k] += __shfl_xor_sync(0xffffffffu, acc[k], off);

    if (lane < 8) {
        float sw = g_selfw[gw];
        uint4 own = hin4[(size_t)gw * 8 + sub];
        const __half2* op = (const __half2*)&own;
#pragma unroll
        for (int q = 0; q < 4; ++q) {
            float2 f = __half22float2(op[q]);
            acc[2 * q]     = fmaf(sw, f.x, acc[2 * q]);
            acc[2 * q + 1] = fmaf(sw, f.y, acc[2 * q + 1]);
        }
        uint4 outv;
        __half2* ov = (__half2*)&outv;
#pragma unroll
        for (int q = 0; q < 4; ++q)
            ov[q] = __floats2half2_rn(acc[2 * q], acc[2 * q + 1]);
        hout4[(size_t)gw * 8 + sub] = outv;

        float4* accp = (float4*)g_acc;
        size_t ai = (size_t)gw * 16 + sub * 2;
        if (iter == 0) {
            accp[ai]     = make_float4(acc[0], acc[1], acc[2], acc[3]);
            accp[ai + 1] = make_float4(acc[4], acc[5], acc[6], acc[7]);
        } else {
            float4 t0 = accp[ai], t1 = accp[ai + 1];
            t0.x += acc[0]; t0.y += acc[1]; t0.z += acc[2]; t0.w += acc[3];
            t1.x += acc[4]; t1.y += acc[5]; t1.z += acc[6]; t1.w += acc[7];
            accp[ai] = t0; accp[ai + 1] = t1;
        }
    }
}

// ---------------- y16 = fp16(0.1x + 0.09acc) --------------------------------
__global__ void ymix_kernel(const float* __restrict__ x, int n2) {
    int i = blockIdx.x * blockDim.x + threadIdx.x;
    if (i < n2) {
        float2 xv = ((const float2*)x)[i];
        float2 av = ((const float2*)g_acc)[i];
        ((__half2*)g_y16)[i] =
            __floats2half2_rn(0.1f * xv.x + 0.09f * av.x,
                              0.1f * xv.y + 0.09f * av.y);
    }
}

// ---------------- mma / ldmatrix wrappers ------------------------------------
__device__ __forceinline__ void mma16816(float* c, uint32_t a0, uint32_t a1,
                                         uint32_t a2, uint32_t a3,
                                         uint32_t b0, uint32_t b1) {
    asm volatile(
        "mma.sync.aligned.m16n8k16.row.col.f32.f16.f16.f32 "
        "{%0,%1,%2,%3}, {%4,%5,%6,%7}, {%8,%9}, {%0,%1,%2,%3};"
        : "+f"(c[0]), "+f"(c[1]), "+f"(c[2]), "+f"(c[3])
        : "r"(a0), "r"(a1), "r"(a2), "r"(a3), "r"(b0), "r"(b1));
}

__device__ __forceinline__ void ldsm_x4(uint32_t& r0, uint32_t& r1,
                                        uint32_t& r2, uint32_t& r3,
                                        uint32_t saddr) {
    asm volatile(
        "ldmatrix.sync.aligned.m8n8.x4.shared.b16 {%0,%1,%2,%3}, [%4];"
        : "=r"(r0), "=r"(r1), "=r"(r2), "=r"(r3) : "r"(saddr));
}

// ---------------- GEMM1 (smem+ldmatrix): z16 = relu(y16 @ W0 + b0) ----------
// block: 64 rows x all 256 cols, 256 thr = 8 warps (4 row-grp x 2 col-half).
// smem rows padded to 72 halfs (144B) -> ldmatrix row ptrs on banks 4r.
__global__ void gemm1_mma(const float* __restrict__ b0v, int M) {
    __shared__ __half Ys[64][72];
    __shared__ __half Ws[256][72];
    int tid = threadIdx.x;
    int wid = tid >> 5, lane = tid & 31;
    int gid = lane >> 2, tig = lane & 3;
    int rowgrp = wid >> 1, colhalf = wid & 1;
    int m0 = blockIdx.x * 64;

#pragma unroll
    for (int i = 0; i < 2; ++i) {
        int u = i * 256 + tid;          // < 512
        int r = u >> 3, c8 = u & 7;
        int gr = min(m0 + r, M - 1);
        uint4 v = ((const uint4*)g_y16)[(size_t)gr * 8 + c8];
        *(uint4*)&Ys[r][c8 * 8] = v;
    }
#pragma unroll
    for (int i = 0; i < 8; ++i) {
        int u = i * 256 + tid;          // < 2048
        int r = u >> 3, c8 = u & 7;
        uint4 v = ((const uint4*)g_w0t)[u];
        *(uint4*)&Ws[r][c8 * 8] = v;
    }
    __syncthreads();

    uint32_t ybase = (uint32_t)__cvta_generic_to_shared(&Ys[0][0]);
    uint32_t wbase = (uint32_t)__cvta_generic_to_shared(&Ws[0][0]);

    int arow   = rowgrp * 16 + (lane & 15);
    int acoff  = (lane >> 4) << 3;               // k offset 0/8
    int bnrow  = (lane & 7) + ((lane >> 4) << 3); // n offset 0..15
    int bkoff  = ((lane >> 3) & 1) << 3;          // k offset 0/8

    float c[16][4];
#pragma unroll
    for (int i = 0; i < 16; ++i)
#pragma unroll
        for (int j = 0; j < 4; ++j) c[i][j] = 0.0f;

#pragma unroll
    for (int ks = 0; ks < 4; ++ks) {
        int kb = ks * 16;
        uint32_t a0, a1, a2, a3;
        ldsm_x4(a0, a1, a2, a3, ybase + (arow * 72 + kb + acoff) * 2);
#pragma unroll
        for (int p = 0; p < 8; ++p) {
            int nn0 = colhalf * 128 + p * 16;
            uint32_t b0, b1, b2, b3;
            ldsm_x4(b0, b1, b2, b3,
                    wbase + ((nn0 + bnrow) * 72 + kb + bkoff) * 2);
            mma16816(c[2 * p],     a0, a1, a2, a3, b0, b1);
            mma16816(c[2 * p + 1], a0, a1, a2, a3, b2, b3);
        }
    }

    int r0 = m0 + rowgrp * 16 + gid;
    int r1 = r0 + 8;
#pragma unroll
    for (int nf = 0; nf < 16; ++nf) {
        int cn = colhalf * 128 + nf * 8 + tig * 2;
        float2 bias = *(const float2*)&b0v[cn];
        if (r0 < M) {
            __half2 h = __floats2half2_rn(fmaxf(c[nf][0] + bias.x, 0.0f),
                                          fmaxf(c[nf][1] + bias.y, 0.0f));
            *(__half2*)&g_z16[(size_t)r0 * 256 + cn] = h;
        }
        if (r1 < M) {
            __half2 h = __floats2half2_rn(fmaxf(c[nf][2] + bias.x, 0.0f),
                                          fmaxf(c[nf][3] + bias.y, 0.0f));
            *(__half2*)&g_z16[(size_t)r1 * 256 + cn] = h;
        }
    }
}

// ---------------- GEMM2 (smem+ldmatrix): out = z16 @ W1 + b1 ----------------
// block: 64 rows x 64 cols, 128 thr = 4 warps (row-groups); K tiled 2 x 128.
__global__ void gemm2_mma(const float* __restrict__ b1v,
                          float* __restrict__ out, int M) {
    __shared__ __half Zs[64][136];
    __shared__ __half W1s[64][136];
    int tid = threadIdx.x;
    int wid = tid >> 5, lane = tid & 31;
    int gid = lane >> 2, tig = lane & 3;
    int m0 = blockIdx.x * 64;

    uint32_t zbase = (uint32_t)__cvta_generic_to_shared(&Zs[0][0]);
    uint32_t wbase = (uint32_t)__cvta_generic_to_shared(&W1s[0][0]);

    int arow  = wid * 16 + (lane & 15);
    int acoff = (lane >> 4) << 3;
    int bnrow = (lane & 7) + ((lane >> 4) << 3);
    int bkoff = ((lane >> 3) & 1) << 3;

    float c[8][4];
#pragma unroll
    for (int i = 0; i < 8; ++i)
#pragma unroll
        for (int j = 0; j < 4; ++j) c[i][j] = 0.0f;

#pragma unroll
    for (int kk = 0; kk < 2; ++kk) {
#pragma unroll
        for (int i = 0; i < 8; ++i) {
            int u = i * 128 + tid;       // < 1024
            int r = u >> 4, c8 = u & 15;
            int gr = min(m0 + r, M - 1);
            uint4 v = ((const uint4*)g_z16)[(size_t)gr * 32 + kk * 16 + c8];
            *(uint4*)&Zs[r][c8 * 8] = v;
        }
#pragma unroll
        for (int i = 0; i < 8; ++i) {
            int u = i * 128 + tid;       // < 1024
            int r = u >> 4, c8 = u & 15;
            uint4 v = ((const uint4*)g_w1t)[r * 32 + kk * 16 + c8];
            *(uint4*)&W1s[r][c8 * 8] = v;
        }
        __syncthreads();

#pragma unroll
        for (int ks = 0; ks < 8; ++ks) {
            int kb = ks * 16;
            uint32_t a0, a1, a2, a3;
            ldsm_x4(a0, a1, a2, a3, zbase + (arow * 136 + kb + acoff) * 2);
#pragma unroll
            for (int p = 0; p < 4; ++p) {
                int nn0 = p * 16;
                uint32_t b0, b1, b2, b3;
                ldsm_x4(b0, b1, b2, b3,
                        wbase + ((nn0 + bnrow) * 136 + kb + bkoff) * 2);
                mma16816(c[2 * p],     a0, a1, a2, a3, b0, b1);
                mma16816(c[2 * p + 1], a0, a1, a2, a3, b2, b3);
            }
        }
        __syncthreads();
    }

    int r0 = m0 + wid * 16 + gid;
    int r1 = r0 + 8;
#pragma unroll
    for (int nf = 0; nf < 8; ++nf) {
        int cn = nf * 8 + tig * 2;
        float2 bias = *(const float2*)&b1v[cn];
        if (r0 < M) {
            float2 o = make_float2(c[nf][0] + bias.x, c[nf][1] + bias.y);
            *(float2*)&out[(size_t)r0 * 64 + cn] = o;
        }
        if (r1 < M) {
            float2 o = make_float2(c[nf][2] + bias.x, c[nf][3] + bias.y);
            *(float2*)&out[(size_t)r1 * 64 + cn] = o;
        }
    }
}

// ---------------- launcher ---------------------------------------------------
extern "C" void kernel_launch(void* const* d_in, const int* in_sizes, int n_in,
                              void* d_out, int out_size) {
    const float* x  = (const float*)d_in[0];
    const int*   ei = (const int*)d_in[1];
    const float* ew = (const float*)d_in[2];
    const float* W0 = (const float*)d_in[3];
    const float* b0 = (const float*)d_in[4];
    const float* W1 = (const float*)d_in[5];
    const float* b1 = (const float*)d_in[6];
    float* out = (float*)d_out;

    int n = in_sizes[0] / DD;
    int e = in_sizes[2];
    const int* row = ei;
    const int* col = ei + e;

    int n2 = n * DD / 2;
    int nb = (n + SC - 1) / SC;   // scan blocks (98 for n=100000)

    init_cvt_kernel<<<(n2 + 255) / 256, 256>>>(x, n, n2);
    hist_kernel<<<(e + 255) / 256, 256>>>(row, ew, e);
    dinv_kernel<<<(n + 255) / 256, 256>>>(n);
    wconv_kernel<<<64, 256>>>(W0, W1);
    scanA_kernel<<<nb, 256>>>(n);
    scanB_kernel<<<1, 128>>>(nb, n);
    scanC_kernel<<<nb, 256>>>(n);
    scatter_kernel<<<(e + 255) / 256, 256>>>(row, col, ew, e);

    int spmm_grid = (n + 7) / 8;   // 8 warps (rows) per 256-thread block
    for (int it = 0; it < KPROP; ++it)
        spmm_kernel<<<spmm_grid, 256>>>(it, n);

    ymix_kernel<<<(n2 + 255) / 256, 256>>>(x, n2);

    int mblocks = (n + 63) / 64;
    gemm1_mma<<<mblocks, 256>>>(b0, n);
    gemm2_mma<<<mblocks, 128>>>(b1, out, n);
}